// round 1
// baseline (speedup 1.0000x reference)
#include <cuda_runtime.h>

#define NN 50000
#define NE 600000
#define FD 128

// ---------------- scratch (device globals; no allocation allowed) ----------
__device__ float g_h[(size_t)NN * FD];   // h = x @ W
__device__ float g_t[(size_t)NN * FD];   // relu(layer1) output
__device__ int   g_cnt[NN];
__device__ int   g_off[NN + 1];
__device__ int   g_cur[NN];
__device__ float g_dinv[NN];
__device__ int   g_eid[NE];
__device__ int   g_esrc[NE];

// ---------------- graph preprocessing -------------------------------------
__global__ void k_zero_cnt() {
    int i = blockIdx.x * blockDim.x + threadIdx.x;
    if (i < NN) g_cnt[i] = 0;
}

__global__ void k_hist(const int* __restrict__ dst) {
    int e = blockIdx.x * blockDim.x + threadIdx.x;
    if (e < NE) atomicAdd(&g_cnt[dst[e]], 1);
}

// single-block exclusive scan over 50000 counts; also dinv = rsqrt(deg+1)
__global__ void k_scan() {
    const int T = 1024;
    const int per = (NN + T - 1) / T;  // 49
    int t  = threadIdx.x;
    int lo = t * per;
    int hi = min(lo + per, NN);
    int s = 0;
    for (int i = lo; i < hi; i++) s += g_cnt[i];
    __shared__ int ps[T];
    ps[t] = s;
    __syncthreads();
    for (int d = 1; d < T; d <<= 1) {
        int v = (t >= d) ? ps[t - d] : 0;
        __syncthreads();
        ps[t] += v;
        __syncthreads();
    }
    int base = (t == 0) ? 0 : ps[t - 1];
    for (int i = lo; i < hi; i++) {
        g_off[i] = base;
        g_cur[i] = base;
        g_dinv[i] = rsqrtf((float)g_cnt[i] + 1.0f);
        base += g_cnt[i];
    }
    if (hi == NN) g_off[NN] = base;  // all tail threads write the same total
}

__global__ void k_scatter(const int* __restrict__ dst) {
    int e = blockIdx.x * blockDim.x + threadIdx.x;
    if (e < NE) {
        int p = atomicAdd(&g_cur[dst[e]], 1);
        g_eid[p] = e;
    }
}

// canonicalize each CSR segment (sort by edge id) so float sum order is
// deterministic across replays, then materialize src ids
__global__ void k_sort(const int* __restrict__ src) {
    int i = blockIdx.x * blockDim.x + threadIdx.x;
    if (i >= NN) return;
    int o  = g_off[i];
    int e1 = g_off[i + 1];
    for (int j = o + 1; j < e1; j++) {
        int key = g_eid[j];
        int k = j - 1;
        while (k >= o && g_eid[k] > key) { g_eid[k + 1] = g_eid[k]; k--; }
        g_eid[k + 1] = key;
    }
    for (int j = o; j < e1; j++) g_esrc[j] = src[g_eid[j]];
}

// ---------------- SGEMM: C[M,128] = A[M,128] @ W[128,128] ------------------
__global__ __launch_bounds__(256, 1) void k_gemm(const float* __restrict__ A,
                                                 const float* __restrict__ W,
                                                 float* __restrict__ C) {
    extern __shared__ float smem[];
    float (*As)[129] = (float(*)[129])smem;                 // [m][k], pad 129
    float (*Bs)[128] = (float(*)[128])(smem + 128 * 129);   // [k][n]
    const int tid = threadIdx.x;
    const int m0  = blockIdx.x * 128;

    // load W (16384 floats)
    {
        const float4* W4  = (const float4*)W;
        float4*       Bs4 = (float4*)Bs;
        #pragma unroll
        for (int i = 0; i < 16; i++) Bs4[tid + i * 256] = W4[tid + i * 256];
    }
    // load A tile, zero-padded at the M tail
    {
        const float4* A4 = (const float4*)A;
        #pragma unroll
        for (int ii = 0; ii < 16; ii++) {
            int i  = tid + ii * 256;
            int m  = i >> 5;
            int k4 = i & 31;
            int gm = m0 + m;
            float4 v = make_float4(0.f, 0.f, 0.f, 0.f);
            if (gm < NN) v = A4[(size_t)gm * 32 + k4];
            As[m][k4 * 4 + 0] = v.x;
            As[m][k4 * 4 + 1] = v.y;
            As[m][k4 * 4 + 2] = v.z;
            As[m][k4 * 4 + 3] = v.w;
        }
    }
    __syncthreads();

    const int tx = tid & 15;   // n-group (8 cols)
    const int ty = tid >> 4;   // m-group (8 rows)
    float acc[8][8];
    #pragma unroll
    for (int i = 0; i < 8; i++)
        #pragma unroll
        for (int j = 0; j < 8; j++) acc[i][j] = 0.f;

    #pragma unroll 8
    for (int k = 0; k < 128; k++) {
        float a[8], b[8];
        #pragma unroll
        for (int i = 0; i < 8; i++) a[i] = As[ty * 8 + i][k];
        float4 b0 = *(const float4*)&Bs[k][tx * 8];
        float4 b1 = *(const float4*)&Bs[k][tx * 8 + 4];
        b[0] = b0.x; b[1] = b0.y; b[2] = b0.z; b[3] = b0.w;
        b[4] = b1.x; b[5] = b1.y; b[6] = b1.z; b[7] = b1.w;
        #pragma unroll
        for (int i = 0; i < 8; i++)
            #pragma unroll
            for (int j = 0; j < 8; j++) acc[i][j] += a[i] * b[j];
    }

    #pragma unroll
    for (int i = 0; i < 8; i++) {
        int gm = m0 + ty * 8 + i;
        if (gm < NN) {
            float4* o = (float4*)&C[(size_t)gm * FD + tx * 8];
            o[0] = make_float4(acc[i][0], acc[i][1], acc[i][2], acc[i][3]);
            o[1] = make_float4(acc[i][4], acc[i][5], acc[i][6], acc[i][7]);
        }
    }
}

// ---------------- aggregation: one warp per dst node -----------------------
// out[d] = sum_{e: dst=d} h[src_e]*dinv[src_e]*dinv[d] + h[d]*dinv[d]^2 + b
__global__ __launch_bounds__(256) void k_agg(const float* __restrict__ h,
                                             const float* __restrict__ bias,
                                             float* __restrict__ out,
                                             int do_relu) {
    int gw   = (blockIdx.x * blockDim.x + threadIdx.x) >> 5;
    int lane = threadIdx.x & 31;
    if (gw >= NN) return;
    int node = gw;
    int e  = g_off[node];
    int e1 = g_off[node + 1];
    float di = g_dinv[node];
    const float4* __restrict__ h4 = (const float4*)h;

    float4 acc = make_float4(0.f, 0.f, 0.f, 0.f);
    for (; e + 1 < e1; e += 2) {
        int sa = g_esrc[e];
        int sb = g_esrc[e + 1];
        float ca = g_dinv[sa] * di;
        float cb = g_dinv[sb] * di;
        float4 va = h4[(size_t)sa * 32 + lane];
        float4 vb = h4[(size_t)sb * 32 + lane];
        acc.x += va.x * ca; acc.y += va.y * ca; acc.z += va.z * ca; acc.w += va.w * ca;
        acc.x += vb.x * cb; acc.y += vb.y * cb; acc.z += vb.z * cb; acc.w += vb.w * cb;
    }
    if (e < e1) {
        int sa = g_esrc[e];
        float ca = g_dinv[sa] * di;
        float4 va = h4[(size_t)sa * 32 + lane];
        acc.x += va.x * ca; acc.y += va.y * ca; acc.z += va.z * ca; acc.w += va.w * ca;
    }
    // self-loop
    float s2 = di * di;
    float4 hv = h4[(size_t)node * 32 + lane];
    acc.x += hv.x * s2; acc.y += hv.y * s2; acc.z += hv.z * s2; acc.w += hv.w * s2;
    // bias
    float4 bv = ((const float4*)bias)[lane];
    acc.x += bv.x; acc.y += bv.y; acc.z += bv.z; acc.w += bv.w;
    if (do_relu) {
        acc.x = fmaxf(acc.x, 0.f); acc.y = fmaxf(acc.y, 0.f);
        acc.z = fmaxf(acc.z, 0.f); acc.w = fmaxf(acc.w, 0.f);
    }
    ((float4*)out)[(size_t)node * 32 + lane] = acc;
}

// ---------------- launch ----------------------------------------------------
extern "C" void kernel_launch(void* const* d_in, const int* in_sizes, int n_in,
                              void* d_out, int out_size) {
    const float* x  = (const float*)d_in[0];
    const int*   ei = (const int*)d_in[1];
    const float* W1 = (const float*)d_in[2];
    const float* b1 = (const float*)d_in[3];
    const float* W2 = (const float*)d_in[4];
    const float* b2 = (const float*)d_in[5];
    const int* src = ei;
    const int* dst = ei + NE;
    float* out = (float*)d_out;

    float *hp, *tp;
    cudaGetSymbolAddress((void**)&hp, g_h);
    cudaGetSymbolAddress((void**)&tp, g_t);

    const int SMEM_GEMM = (128 * 129 + 128 * 128) * 4;  // 131584 B
    cudaFuncSetAttribute(k_gemm, cudaFuncAttributeMaxDynamicSharedMemorySize, SMEM_GEMM);

    // graph preprocessing (deterministic CSR)
    k_zero_cnt<<<(NN + 255) / 256, 256>>>();
    k_hist<<<(NE + 255) / 256, 256>>>(dst);
    k_scan<<<1, 1024>>>();
    k_scatter<<<(NE + 255) / 256, 256>>>(dst);
    k_sort<<<(NN + 255) / 256, 256>>>(src);

    // layer 1: h = x@W1; agg + self + b1; relu -> g_t
    k_gemm<<<(NN + 127) / 128, 256, SMEM_GEMM>>>(x, W1, hp);
    k_agg<<<(NN * 32 + 255) / 256, 256>>>(hp, b1, tp, 1);

    // layer 2: h = t@W2; agg + self + b2 -> out
    k_gemm<<<(NN + 127) / 128, 256, SMEM_GEMM>>>(tp, W2, hp);
    k_agg<<<(NN * 32 + 255) / 256, 256>>>(hp, b2, out, 0);
}

// round 5
// speedup vs baseline: 1.8742x; 1.8742x over previous
#include <cuda_runtime.h>
#include <cuda_bf16.h>
#include <cstdint>

#define NN 50000
#define NE 600000
#define FD 128

// ---------------- scratch ---------------------------------------------------
__device__ float g_h[(size_t)NN * FD];
__device__ float g_t[(size_t)NN * FD];
__device__ int   g_cnt[NN];
__device__ int   g_off[NN + 1];
__device__ int   g_cur[NN];
__device__ float g_dinv[NN];
__device__ int   g_eid[NE];
__device__ int   g_esrc[NE];
__device__ int   g_part[256];
// W fragments in mma.m16n8k16 per-lane register order:
// [layer][pass(hi/lo)][ktile 8][ntile 16][reg 2][lane 32] u32
__device__ uint32_t g_wfrag[2][2][8][16][2][32];

// ---------------- mma helper ------------------------------------------------
__device__ __forceinline__ void mma16816(float* c, const uint32_t* a, const uint32_t* b) {
    asm volatile(
        "mma.sync.aligned.m16n8k16.row.col.f32.bf16.bf16.f32 "
        "{%0,%1,%2,%3}, {%4,%5,%6,%7}, {%8,%9}, {%0,%1,%2,%3};"
        : "+f"(c[0]), "+f"(c[1]), "+f"(c[2]), "+f"(c[3])
        : "r"(a[0]), "r"(a[1]), "r"(a[2]), "r"(a[3]), "r"(b[0]), "r"(b[1]));
}
__device__ __forceinline__ uint32_t pack_bf16(float lo, float hi) {
    __nv_bfloat16 a = __float2bfloat16(lo);
    __nv_bfloat16 b = __float2bfloat16(hi);
    uint16_t ua = *(uint16_t*)&a, ub = *(uint16_t*)&b;
    return ((uint32_t)ub << 16) | ua;
}

// ---------------- graph preprocessing --------------------------------------
__global__ void k_zero_cnt() {
    int i = blockIdx.x * blockDim.x + threadIdx.x;
    if (i < NN) g_cnt[i] = 0;
}

__global__ void k_hist(const int* __restrict__ dst) {
    int t = blockIdx.x * blockDim.x + threadIdx.x;
    int e = t * 4;
    if (e + 3 < NE) {
        int4 d = *(const int4*)(dst + e);
        atomicAdd(&g_cnt[d.x], 1);
        atomicAdd(&g_cnt[d.y], 1);
        atomicAdd(&g_cnt[d.z], 1);
        atomicAdd(&g_cnt[d.w], 1);
    } else {
        for (; e < NE; e++) atomicAdd(&g_cnt[dst[e]], 1);
    }
}

__global__ void k_scan1() {
    __shared__ int sh[256];
    int t = threadIdx.x;
    int i = blockIdx.x * 256 + t;
    int v = (i < NN) ? g_cnt[i] : 0;
    int acc = v;
    sh[t] = acc;
    __syncthreads();
    #pragma unroll
    for (int d = 1; d < 256; d <<= 1) {
        int u = (t >= d) ? sh[t - d] : 0;
        __syncthreads();
        acc += u;
        sh[t] = acc;
        __syncthreads();
    }
    if (i < NN) g_off[i] = acc - v;
    if (t == 255) g_part[blockIdx.x] = acc;
}

__global__ void k_scan2() {
    __shared__ int sh[256];
    int t = threadIdx.x;
    int v = (t < 196) ? g_part[t] : 0;
    int acc = v;
    sh[t] = acc;
    __syncthreads();
    #pragma unroll
    for (int d = 1; d < 256; d <<= 1) {
        int u = (t >= d) ? sh[t - d] : 0;
        __syncthreads();
        acc += u;
        sh[t] = acc;
        __syncthreads();
    }
    g_part[t] = acc - v;
}

__global__ void k_scan3() {
    int i = blockIdx.x * blockDim.x + threadIdx.x;
    if (i < NN) {
        int o = g_off[i] + g_part[blockIdx.x];
        g_off[i] = o;
        g_cur[i] = o;
        g_dinv[i] = rsqrtf((float)g_cnt[i] + 1.0f);
    }
    if (i == 0) g_off[NN] = NE;
}

__global__ void k_scatter(const int* __restrict__ dst) {
    int t = blockIdx.x * blockDim.x + threadIdx.x;
    int e = t * 4;
    if (e + 3 < NE) {
        int4 d = *(const int4*)(dst + e);
        int p0 = atomicAdd(&g_cur[d.x], 1);
        int p1 = atomicAdd(&g_cur[d.y], 1);
        int p2 = atomicAdd(&g_cur[d.z], 1);
        int p3 = atomicAdd(&g_cur[d.w], 1);
        g_eid[p0] = e; g_eid[p1] = e + 1; g_eid[p2] = e + 2; g_eid[p3] = e + 3;
    } else {
        for (; e < NE; e++) { int p = atomicAdd(&g_cur[dst[e]], 1); g_eid[p] = e; }
    }
}

// sort each CSR segment by edge id -> deterministic float sum order
__global__ void k_sort(const int* __restrict__ src) {
    int i = blockIdx.x * blockDim.x + threadIdx.x;
    if (i >= NN) return;
    int o = g_off[i], e1 = g_off[i + 1];
    for (int j = o + 1; j < e1; j++) {
        int key = g_eid[j];
        int k = j - 1;
        while (k >= o && g_eid[k] > key) { g_eid[k + 1] = g_eid[k]; k--; }
        g_eid[k + 1] = key;
    }
    for (int j = o; j < e1; j++) g_esrc[j] = src[g_eid[j]];
}

// ---------------- weight fragment prep -------------------------------------
// one thread per u32 fragment entry: 2 layers * 2 pass * 8 kt * 16 nt * 2 reg * 32 lanes
__global__ void k_prepw(const float* __restrict__ W1, const float* __restrict__ W2) {
    int idx = blockIdx.x * blockDim.x + threadIdx.x;  // 0..32767
    int lane = idx & 31;
    int reg  = (idx >> 5) & 1;
    int nt   = (idx >> 6) & 15;
    int kt   = (idx >> 10) & 7;
    int pass = (idx >> 13) & 1;
    int layer = (idx >> 14) & 1;
    const float* W = layer ? W2 : W1;
    int k = kt * 16 + (lane & 3) * 2 + reg * 8;
    int n = nt * 8 + (lane >> 2);
    float v0 = W[k * FD + n];
    float v1 = W[(k + 1) * FD + n];
    uint32_t out;
    if (pass == 0) {
        out = pack_bf16(v0, v1);
    } else {
        __nv_bfloat16 h0 = __float2bfloat16(v0);
        __nv_bfloat16 h1 = __float2bfloat16(v1);
        out = pack_bf16(v0 - __bfloat162float(h0), v1 - __bfloat162float(h1));
    }
    g_wfrag[layer][pass][kt][nt][reg][lane] = out;
}

// ---------------- tensor-core GEMM: C[M,128] = A[M,128] @ W ----------------
// A split into bf16 hi/lo in smem (pitch 68 words = 136 bf16, conflict-free)
#define APITCH 68
#define SM_WORDS (2 * 128 * APITCH)   // 17408 u32 = 69632 B

__global__ __launch_bounds__(256, 1) void k_gemm_mma(const float* __restrict__ A,
                                                     const uint32_t* __restrict__ WF,
                                                     float* __restrict__ C) {
    extern __shared__ uint32_t sA[];   // [hi 128][APITCH], then [lo]
    uint32_t* sHi = sA;
    uint32_t* sLo = sA + 128 * APITCH;
    const int tid = threadIdx.x;
    const int lane = tid & 31;
    const int w = tid >> 5;
    const int wm = w & 3;     // M group: rows wm*32
    const int wn = w >> 2;    // N group: cols wn*64
    const int m0 = blockIdx.x * 128;

    // load + split A tile: 128 rows x 32 float4
    const float4* A4 = (const float4*)A;
    #pragma unroll
    for (int i = 0; i < 16; i++) {
        int idx = tid + i * 256;
        int row = idx >> 5, c4 = idx & 31;
        int gm = m0 + row;
        float4 v = make_float4(0.f, 0.f, 0.f, 0.f);
        if (gm < NN) v = A4[(size_t)gm * 32 + c4];
        __nv_bfloat16 hx = __float2bfloat16(v.x), hy = __float2bfloat16(v.y);
        __nv_bfloat16 hz = __float2bfloat16(v.z), hw = __float2bfloat16(v.w);
        int wd = row * APITCH + c4 * 2;
        sHi[wd]     = pack_bf16(v.x, v.y);
        sHi[wd + 1] = pack_bf16(v.z, v.w);
        sLo[wd]     = pack_bf16(v.x - __bfloat162float(hx), v.y - __bfloat162float(hy));
        sLo[wd + 1] = pack_bf16(v.z - __bfloat162float(hz), v.w - __bfloat162float(hw));
    }
    __syncthreads();

    float acc[2][8][4];
    #pragma unroll
    for (int m = 0; m < 2; m++)
        #pragma unroll
        for (int j = 0; j < 8; j++)
            #pragma unroll
            for (int q = 0; q < 4; q++) acc[m][j][q] = 0.f;

    const int r = lane >> 2;
    const int kq = lane & 3;

    #pragma unroll
    for (int kt = 0; kt < 8; kt++) {
        // A fragments (hi & lo) for 2 mtiles
        uint32_t ah[2][4], al[2][4];
        #pragma unroll
        for (int m = 0; m < 2; m++) {
            int row0 = wm * 32 + m * 16 + r;
            int b0 = row0 * APITCH + kt * 8 + kq;
            int b1 = (row0 + 8) * APITCH + kt * 8 + kq;
            ah[m][0] = sHi[b0];     ah[m][1] = sHi[b1];
            ah[m][2] = sHi[b0 + 4]; ah[m][3] = sHi[b1 + 4];
            al[m][0] = sLo[b0];     al[m][1] = sLo[b1];
            al[m][2] = sLo[b0 + 4]; al[m][3] = sLo[b1 + 4];
        }
        // B fragments: hi & lo for 8 ntiles (coalesced, L1-resident)
        // layout stride: per ntile = 2 regs * 32 lanes = 64 u32; per reg = 32
        uint32_t bh[8][2], bl[8][2];
        const uint32_t* ph = WF + (((0 * 8 + kt) * 16 + wn * 8) * 2) * 32 + lane;
        const uint32_t* pl = WF + (((1 * 8 + kt) * 16 + wn * 8) * 2) * 32 + lane;
        #pragma unroll
        for (int j = 0; j < 8; j++) {
            bh[j][0] = __ldg(ph + j * 64);
            bh[j][1] = __ldg(ph + j * 64 + 32);
            bl[j][0] = __ldg(pl + j * 64);
            bl[j][1] = __ldg(pl + j * 64 + 32);
        }
        #pragma unroll
        for (int m = 0; m < 2; m++)
            #pragma unroll
            for (int j = 0; j < 8; j++) {
                mma16816(acc[m][j], ah[m], bh[j]);
                mma16816(acc[m][j], ah[m], bl[j]);
                mma16816(acc[m][j], al[m], bh[j]);
            }
    }

    // epilogue
    #pragma unroll
    for (int m = 0; m < 2; m++) {
        int gr0 = m0 + wm * 32 + m * 16 + r;
        int gr1 = gr0 + 8;
        #pragma unroll
        for (int j = 0; j < 8; j++) {
            int col = wn * 64 + j * 8 + kq * 2;
            if (gr0 < NN) *(float2*)&C[(size_t)gr0 * FD + col] = make_float2(acc[m][j][0], acc[m][j][1]);
            if (gr1 < NN) *(float2*)&C[(size_t)gr1 * FD + col] = make_float2(acc[m][j][2], acc[m][j][3]);
        }
    }
}

// ---------------- aggregation: one warp per dst node ------------------------
__global__ __launch_bounds__(256) void k_agg(const float* __restrict__ h,
                                             const float* __restrict__ bias,
                                             float* __restrict__ out,
                                             int do_relu) {
    int gw = (blockIdx.x * blockDim.x + threadIdx.x) >> 5;
    int lane = threadIdx.x & 31;
    if (gw >= NN) return;
    int node = gw;
    int e = g_off[node];
    int e1 = g_off[node + 1];
    float di = g_dinv[node];
    const float4* __restrict__ h4 = (const float4*)h;

    float4 acc = make_float4(0.f, 0.f, 0.f, 0.f);
    for (; e + 1 < e1; e += 2) {
        int sa = g_esrc[e];
        int sb = g_esrc[e + 1];
        float ca = g_dinv[sa] * di;
        float cb = g_dinv[sb] * di;
        float4 va = h4[(size_t)sa * 32 + lane];
        float4 vb = h4[(size_t)sb * 32 + lane];
        acc.x += va.x * ca; acc.y += va.y * ca; acc.z += va.z * ca; acc.w += va.w * ca;
        acc.x += vb.x * cb; acc.y += vb.y * cb; acc.z += vb.z * cb; acc.w += vb.w * cb;
    }
    if (e < e1) {
        int sa = g_esrc[e];
        float ca = g_dinv[sa] * di;
        float4 va = h4[(size_t)sa * 32 + lane];
        acc.x += va.x * ca; acc.y += va.y * ca; acc.z += va.z * ca; acc.w += va.w * ca;
    }
    float s2 = di * di;
    float4 hv = h4[(size_t)node * 32 + lane];
    acc.x += hv.x * s2; acc.y += hv.y * s2; acc.z += hv.z * s2; acc.w += hv.w * s2;
    float4 bv = ((const float4*)bias)[lane];
    acc.x += bv.x; acc.y += bv.y; acc.z += bv.z; acc.w += bv.w;
    if (do_relu) {
        acc.x = fmaxf(acc.x, 0.f); acc.y = fmaxf(acc.y, 0.f);
        acc.z = fmaxf(acc.z, 0.f); acc.w = fmaxf(acc.w, 0.f);
    }
    ((float4*)out)[(size_t)node * 32 + lane] = acc;
}

// ---------------- launch ----------------------------------------------------
extern "C" void kernel_launch(void* const* d_in, const int* in_sizes, int n_in,
                              void* d_out, int out_size) {
    const float* x  = (const float*)d_in[0];
    const int*   ei = (const int*)d_in[1];
    const float* W1 = (const float*)d_in[2];
    const float* b1 = (const float*)d_in[3];
    const float* W2 = (const float*)d_in[4];
    const float* b2 = (const float*)d_in[5];
    const int* src = ei;
    const int* dst = ei + NE;
    float* out = (float*)d_out;

    float *hp, *tp;
    uint32_t* wf;
    cudaGetSymbolAddress((void**)&hp, g_h);
    cudaGetSymbolAddress((void**)&tp, g_t);
    cudaGetSymbolAddress((void**)&wf, g_wfrag);

    const int SMEM = SM_WORDS * 4;  // 69632 B
    cudaFuncSetAttribute(k_gemm_mma, cudaFuncAttributeMaxDynamicSharedMemorySize, SMEM);

    k_zero_cnt<<<196, 256>>>();
    k_hist<<<(NE / 4 + 255) / 256, 256>>>(dst);
    k_scan1<<<196, 256>>>();
    k_scan2<<<1, 256>>>();
    k_scan3<<<196, 256>>>();
    k_scatter<<<(NE / 4 + 255) / 256, 256>>>(dst);
    k_sort<<<(NN + 255) / 256, 256>>>(src);
    k_prepw<<<128, 256>>>(W1, W2);

    const int LW = 2 * 2 * 8 * 16 * 2 * 32 / 2;  // u32 per layer = 16384
    k_gemm_mma<<<(NN + 127) / 128, 256, SMEM>>>(x, wf, hp);
    k_agg<<<(NN * 32 + 255) / 256, 256>>>(hp, b1, tp, 1);
    k_gemm_mma<<<(NN + 127) / 128, 256, SMEM>>>(tp, wf + LW, hp);
    k_agg<<<(NN * 32 + 255) / 256, 256>>>(hp, b2, out, 0);
}